// round 8
// baseline (speedup 1.0000x reference)
#include <cuda_runtime.h>

// Round 6: rebalanced warp specialization.
//   warps 0-7  (producers): stream neighbors of tile t+GRID -> smem cat tile
//   warps 8-11 (consumers): column-paired FFMA2 GEMM of tile t, two 4-row passes
// 2 blocks/SM, 24 warps/SM. Memory is the pole; producers doubled.

#define N_NODES 50000
#define S_NEIGH 25
#define DIM     128
#define OUTD    128
#define KDIM    256
#define TM      32
#define THREADS 384
#define PTHREADS 256            // producer threads (warps 0-7)
#define A_STRIDE 260            // floats per tile row (pad, 16B-aligned)
#define NT      3125            // 2*N_NODES / TM
#define GRID    296             // 2 persistent blocks per SM

typedef unsigned long long u64;

// ---- packed f32x2 helpers ----
__device__ __forceinline__ u64 fadd2(u64 a, u64 b) {
    u64 d; asm("add.rn.f32x2 %0, %1, %2;" : "=l"(d) : "l"(a), "l"(b)); return d;
}
__device__ __forceinline__ u64 fmul2(u64 a, u64 b) {
    u64 d; asm("mul.rn.f32x2 %0, %1, %2;" : "=l"(d) : "l"(a), "l"(b)); return d;
}
__device__ __forceinline__ u64 ffma2(u64 a, u64 b, u64 c) {
    u64 d; asm("fma.rn.f32x2 %0, %1, %2, %3;" : "=l"(d) : "l"(a), "l"(b), "l"(c)); return d;
}
__device__ __forceinline__ u64 bcast2(float x) {          // {x, x}
    u64 d; asm("mov.b64 %0, {%1, %1};" : "=l"(d) : "f"(x)); return d;
}
// 16B streaming load (evict-first; the 1.28GB stream must not thrash caches)
__device__ __forceinline__ ulonglong2 ldcs16(const float* p) {
    ulonglong2 v;
    asm volatile("ld.global.cs.v2.u64 {%0, %1}, [%2];" : "=l"(v.x), "=l"(v.y) : "l"(p));
    return v;
}
__device__ __forceinline__ float4 ld4(const float* p) {
    return *reinterpret_cast<const float4*>(p);
}

// ---- producer: build cat tile rows [x | mean(neg)] ----
__device__ __forceinline__ void produce_tile(
    float* __restrict__ Adst, int tile,
    const float* __restrict__ src, const float* __restrict__ src_neg,
    const float* __restrict__ dst, const float* __restrict__ dst_neg,
    int ptid, int pthreads, u64 inv2)
{
    const long t0 = (long)tile * TM;
    for (int i = ptid; i < TM * (DIM / 4); i += pthreads) {
        const int r  = i >> 5;            // row 0..31
        const int d4 = (i & 31) << 2;     // feature chunk
        const long task = t0 + r;

        const float* xp; const float* np;
        if (task < N_NODES) {
            xp = src + task * DIM;
            np = src_neg + task * (long)(S_NEIGH * DIM);
        } else {
            const long rr = task - N_NODES;
            xp = dst + rr * DIM;
            np = dst_neg + rr * (long)(S_NEIGH * DIM);
        }

        // two independent partial chains shorten the FADD2 dependency
        u64 s0a = 0ull, s1a = 0ull, s0b = 0ull, s1b = 0ull;
        const float* p = np + d4;
        #pragma unroll
        for (int j = 0; j < S_NEIGH - 1; j += 2) {
            const ulonglong2 va = ldcs16(p + j * DIM);
            const ulonglong2 vb = ldcs16(p + (j + 1) * DIM);
            s0a = fadd2(s0a, va.x); s1a = fadd2(s1a, va.y);
            s0b = fadd2(s0b, vb.x); s1b = fadd2(s1b, vb.y);
        }
        {   // last (odd) neighbor
            const ulonglong2 v = ldcs16(p + (S_NEIGH - 1) * DIM);
            s0a = fadd2(s0a, v.x); s1a = fadd2(s1a, v.y);
        }
        const ulonglong2 xv = *reinterpret_cast<const ulonglong2*>(xp + d4);

        ulonglong2 m;
        m.x = fmul2(fadd2(s0a, s0b), inv2);
        m.y = fmul2(fadd2(s1a, s1b), inv2);

        *reinterpret_cast<ulonglong2*>(Adst + r * A_STRIDE + d4)       = xv;
        *reinterpret_cast<ulonglong2*>(Adst + r * A_STRIDE + DIM + d4) = m;
    }
}

__global__ __launch_bounds__(THREADS, 2)
void magg_kernel(const float* __restrict__ src,
                 const float* __restrict__ src_neg,
                 const float* __restrict__ dst,
                 const float* __restrict__ dst_neg,
                 const float* __restrict__ w,
                 float* __restrict__ out)
{
    __shared__ float A[2][TM][A_STRIDE];   // 66.6 KB double buffer

    const int tid  = threadIdx.x;
    const int wid  = tid >> 5;
    const int lane = tid & 31;

    u64 inv2; asm("mov.b64 %0, {%1, %1};" : "=l"(inv2) : "f"(1.0f / (float)S_NEIGH));

    produce_tile(&A[0][0][0], blockIdx.x, src, src_neg, dst, dst_neg,
                 tid, THREADS, inv2);
    __syncthreads();

    int buf = 0;
    for (int t = blockIdx.x; t < NT; t += GRID) {
        const int nxt = t + GRID;

        if (wid < 8) {
            // -------- producers: build tile t+GRID --------
            if (nxt < NT) {
                produce_tile(&A[buf ^ 1][0][0], nxt, src, src_neg, dst, dst_neg,
                             tid, PTHREADS, inv2);
            }
        } else {
            // -------- consumers: column-paired FFMA2 GEMM of tile t --------
            // warp cw: rows 8cw..8cw+7 in two passes of 4 rows (reg budget 80)
            const int cw = wid - 8;
            const int c0 = lane << 2;
            const float* Ab = &A[buf][0][0];

            #pragma unroll
            for (int g = 0; g < 2; g++) {
                const int rg = (cw << 3) + (g << 2);   // first row of this pass

                u64 acc[4][2];
                #pragma unroll
                for (int j = 0; j < 4; j++) { acc[j][0] = 0ull; acc[j][1] = 0ull; }

                #pragma unroll 4
                for (int k4 = 0; k4 < KDIM / 4; k4++) {
                    float4 a[4];
                    #pragma unroll
                    for (int j = 0; j < 4; j++)
                        a[j] = ld4(Ab + (rg + j) * A_STRIDE + (k4 << 2)); // broadcast LDS.128

                    #pragma unroll
                    for (int kk = 0; kk < 4; kk++) {
                        const float4 wv = ld4(w + (long)((k4 << 2) + kk) * OUTD + c0);
                        const u64 wp0 = reinterpret_cast<const u64*>(&wv)[0];
                        const u64 wp1 = reinterpret_cast<const u64*>(&wv)[1];
                        #pragma unroll
                        for (int j = 0; j < 4; j++) {
                            const u64 ap = bcast2((&a[j].x)[kk]);   // ALU-pipe pack
                            acc[j][0] = ffma2(ap, wp0, acc[j][0]);
                            acc[j][1] = ffma2(ap, wp1, acc[j][1]);
                        }
                    }
                }

                const long row0 = (long)t * TM + rg;
                float* o = out + row0 * OUTD + c0;
                #pragma unroll
                for (int j = 0; j < 4; j++) {
                    ulonglong2 r; r.x = acc[j][0]; r.y = acc[j][1];
                    *reinterpret_cast<ulonglong2*>(o + (long)j * OUTD) = r;
                }
            }
        }

        __syncthreads();
        buf ^= 1;
    }
}

extern "C" void kernel_launch(void* const* d_in, const int* in_sizes, int n_in,
                              void* d_out, int out_size)
{
    const float* src     = (const float*)d_in[0];
    const float* src_neg = (const float*)d_in[1];
    const float* dst     = (const float*)d_in[2];
    const float* dst_neg = (const float*)d_in[3];
    const float* w       = (const float*)d_in[4];
    float* out = (float*)d_out;

    magg_kernel<<<GRID, THREADS>>>(src, src_neg, dst, dst_neg, w, out);
}

// round 9
// speedup vs baseline: 1.5451x; 1.5451x over previous
#include <cuda_runtime.h>

// Round 9: R5 structure (4 producer + 4 consumer warps, 256 thr, 2 blocks/SM)
// with producer MLP doubled:
//   - streaming loads are non-volatile asm -> ptxas may batch/hoist them
//   - each producer iteration handles TWO row-items with interleaved loads
// Consumer: column-paired FFMA2 GEMM (unchanged from the 237us kernel).

#define N_NODES 50000
#define S_NEIGH 25
#define DIM     128
#define OUTD    128
#define KDIM    256
#define TM      32
#define THREADS 256
#define A_STRIDE 260            // floats per tile row (pad, 16B-aligned)
#define NT      3125            // 2*N_NODES / TM
#define GRID    296             // 2 persistent blocks per SM

typedef unsigned long long u64;

// ---- packed f32x2 helpers ----
__device__ __forceinline__ u64 fadd2(u64 a, u64 b) {
    u64 d; asm("add.rn.f32x2 %0, %1, %2;" : "=l"(d) : "l"(a), "l"(b)); return d;
}
__device__ __forceinline__ u64 fmul2(u64 a, u64 b) {
    u64 d; asm("mul.rn.f32x2 %0, %1, %2;" : "=l"(d) : "l"(a), "l"(b)); return d;
}
__device__ __forceinline__ u64 ffma2(u64 a, u64 b, u64 c) {
    u64 d; asm("fma.rn.f32x2 %0, %1, %2, %3;" : "=l"(d) : "l"(a), "l"(b), "l"(c)); return d;
}
__device__ __forceinline__ u64 bcast2(float x) {          // {x, x}
    u64 d; asm("mov.b64 %0, {%1, %1};" : "=l"(d) : "f"(x)); return d;
}
// 16B streaming load, evict-first. NOT volatile: the compiler may reorder /
// software-pipeline these, which is exactly what we want for MLP.
__device__ __forceinline__ ulonglong2 ldcs16(const float* p) {
    ulonglong2 v;
    asm("ld.global.cs.v2.u64 {%0, %1}, [%2];" : "=l"(v.x), "=l"(v.y) : "l"(p));
    return v;
}
__device__ __forceinline__ float4 ld4(const float* p) {
    return *reinterpret_cast<const float4*>(p);
}

// ---- producer: build cat tile rows [x | mean(neg)], 2 items per iteration ----
__device__ __forceinline__ void produce_tile(
    float* __restrict__ Adst, int tile,
    const float* __restrict__ src, const float* __restrict__ src_neg,
    const float* __restrict__ dst, const float* __restrict__ dst_neg,
    int ptid, int pthreads, u64 inv2)
{
    const long t0 = (long)tile * TM;
    // 1024 items total; 1024 % (2*pthreads) == 0 for pthreads in {128, 256}
    for (int i = ptid; i < TM * (DIM / 4); i += 2 * pthreads) {
        const int ia = i;
        const int ib = i + pthreads;

        const int ra  = ia >> 5, d4a = (ia & 31) << 2;
        const int rb  = ib >> 5, d4b = (ib & 31) << 2;

        const float *xpa, *npa, *xpb, *npb;
        {
            const long task = t0 + ra;
            if (task < N_NODES) { xpa = src + task * DIM; npa = src_neg + task * (long)(S_NEIGH * DIM); }
            else { const long rr = task - N_NODES; xpa = dst + rr * DIM; npa = dst_neg + rr * (long)(S_NEIGH * DIM); }
        }
        {
            const long task = t0 + rb;
            if (task < N_NODES) { xpb = src + task * DIM; npb = src_neg + task * (long)(S_NEIGH * DIM); }
            else { const long rr = task - N_NODES; xpb = dst + rr * DIM; npb = dst_neg + rr * (long)(S_NEIGH * DIM); }
        }

        const float* pa = npa + d4a;
        const float* pb = npb + d4b;

        u64 sa0 = 0ull, sa1 = 0ull, sb0 = 0ull, sb1 = 0ull;
        #pragma unroll
        for (int j = 0; j < S_NEIGH; j++) {
            const ulonglong2 va = ldcs16(pa + j * DIM);
            const ulonglong2 vb = ldcs16(pb + j * DIM);
            sa0 = fadd2(sa0, va.x); sa1 = fadd2(sa1, va.y);
            sb0 = fadd2(sb0, vb.x); sb1 = fadd2(sb1, vb.y);
        }

        const ulonglong2 xva = *reinterpret_cast<const ulonglong2*>(xpa + d4a);
        const ulonglong2 xvb = *reinterpret_cast<const ulonglong2*>(xpb + d4b);

        ulonglong2 ma, mb;
        ma.x = fmul2(sa0, inv2); ma.y = fmul2(sa1, inv2);
        mb.x = fmul2(sb0, inv2); mb.y = fmul2(sb1, inv2);

        *reinterpret_cast<ulonglong2*>(Adst + ra * A_STRIDE + d4a)       = xva;
        *reinterpret_cast<ulonglong2*>(Adst + ra * A_STRIDE + DIM + d4a) = ma;
        *reinterpret_cast<ulonglong2*>(Adst + rb * A_STRIDE + d4b)       = xvb;
        *reinterpret_cast<ulonglong2*>(Adst + rb * A_STRIDE + DIM + d4b) = mb;
    }
}

__global__ __launch_bounds__(THREADS, 2)
void magg_kernel(const float* __restrict__ src,
                 const float* __restrict__ src_neg,
                 const float* __restrict__ dst,
                 const float* __restrict__ dst_neg,
                 const float* __restrict__ w,
                 float* __restrict__ out)
{
    __shared__ float A[2][TM][A_STRIDE];   // 66.6 KB double buffer

    const int tid  = threadIdx.x;
    const int wid  = tid >> 5;
    const int lane = tid & 31;

    u64 inv2; asm("mov.b64 %0, {%1, %1};" : "=l"(inv2) : "f"(1.0f / (float)S_NEIGH));

    produce_tile(&A[0][0][0], blockIdx.x, src, src_neg, dst, dst_neg,
                 tid, THREADS, inv2);
    __syncthreads();

    int buf = 0;
    for (int t = blockIdx.x; t < NT; t += GRID) {
        const int nxt = t + GRID;

        if (wid < 4) {
            // -------- producers: build tile t+GRID --------
            if (nxt < NT) {
                produce_tile(&A[buf ^ 1][0][0], nxt, src, src_neg, dst, dst_neg,
                             tid, 128, inv2);
            }
        } else {
            // -------- consumers: column-paired FFMA2 GEMM of tile t --------
            // warp cw: rows 8cw..8cw+7; lane: cols 4*lane..4*lane+3 (2 pairs)
            const int cw = wid - 4;
            const int r0 = cw << 3;
            const int c0 = lane << 2;
            const float* Ab = &A[buf][0][0];

            u64 acc[8][2];
            #pragma unroll
            for (int j = 0; j < 8; j++) { acc[j][0] = 0ull; acc[j][1] = 0ull; }

            #pragma unroll 4
            for (int k4 = 0; k4 < KDIM / 4; k4++) {
                float4 a[8];
                #pragma unroll
                for (int j = 0; j < 8; j++)
                    a[j] = ld4(Ab + (r0 + j) * A_STRIDE + (k4 << 2));  // broadcast LDS.128

                #pragma unroll
                for (int kk = 0; kk < 4; kk++) {
                    const float4 wv = ld4(w + (long)((k4 << 2) + kk) * OUTD + c0);
                    const u64 wp0 = reinterpret_cast<const u64*>(&wv)[0];
                    const u64 wp1 = reinterpret_cast<const u64*>(&wv)[1];
                    #pragma unroll
                    for (int j = 0; j < 8; j++) {
                        const u64 ap = bcast2((&a[j].x)[kk]);   // ALU-pipe pack
                        acc[j][0] = ffma2(ap, wp0, acc[j][0]);
                        acc[j][1] = ffma2(ap, wp1, acc[j][1]);
                    }
                }
            }

            const long row0 = (long)t * TM + r0;
            float* o = out + row0 * OUTD + c0;
            #pragma unroll
            for (int j = 0; j < 8; j++) {
                ulonglong2 r; r.x = acc[j][0]; r.y = acc[j][1];
                *reinterpret_cast<ulonglong2*>(o + (long)j * OUTD) = r;
            }
        }

        __syncthreads();
        buf ^= 1;
    }
}

extern "C" void kernel_launch(void* const* d_in, const int* in_sizes, int n_in,
                              void* d_out, int out_size)
{
    const float* src     = (const float*)d_in[0];
    const float* src_neg = (const float*)d_in[1];
    const float* dst     = (const float*)d_in[2];
    const float* dst_neg = (const float*)d_in[3];
    const float* w       = (const float*)d_in[4];
    float* out = (float*)d_out;

    magg_kernel<<<GRID, THREADS>>>(src, src_neg, dst, dst_neg, w, out);
}